// round 1
// baseline (speedup 1.0000x reference)
#include <cuda_runtime.h>
#include <cstdint>

// ---------------------------------------------------------------------------
// SSIM loss, fused single-pass tiled kernel.
//   - 5 depthwise 11x11 Gaussian convs done as separable 1-D convs in SMEM
//   - per-pixel SSIM + hierarchical reduction -> one atomicAdd(double)/block
// Shapes fixed by the problem: (16,3,512,512) fp32 inputs, scalar fp32 out.
// ---------------------------------------------------------------------------

#define IMG_W   512
#define IMG_H   512
#define NPLANES 48                       // 16 * 3
#define NPIX    (48LL * 512 * 512)       // 12,582,912

#define TILE 64
#define HALO 5
#define RW   (TILE + 2 * HALO)           // 74 (region width)
#define RH   (TILE + 2 * HALO)           // 74 (region height)
#define RS   75                          // raw smem row stride (odd, conflict-friendly)
#define HS   65                          // hbuf row stride

// 1-D Gaussian, sigma=1.5, 11 taps, normalized (matches reference to ~1e-7)
#define GW {0.00102838f, 0.00759876f, 0.03600077f, 0.10936070f, 0.21300554f, \
            0.26601172f, 0.21300554f, 0.10936070f, 0.03600077f, 0.00759876f, \
            0.00102838f}

#define C1_ 0.0001f
#define C2_ 0.0009f

__device__ double g_sum;

__global__ void zero_kernel() { g_sum = 0.0; }

__global__ void finalize_kernel(float* out) {
    out[0] = (float)(1.0 - g_sum / (double)NPIX);
}

// Vertical conv pass: 18 strided SMEM loads -> 8 outputs (register tiling).
__device__ __forceinline__ void vpass(const float* __restrict__ col, float out[8]) {
    const float G[11] = GW;
    #pragma unroll
    for (int j = 0; j < 8; j++) out[j] = 0.f;
    #pragma unroll
    for (int k = 0; k < 18; k++) {
        float v = col[k * HS];
        #pragma unroll
        for (int j = 0; j < 8; j++) {
            int t = k - j;
            if (t >= 0 && t < 11) out[j] = fmaf(G[t], v, out[j]);
        }
    }
}

__global__ __launch_bounds__(512, 1)
void ssim_kernel(const float* __restrict__ img1, const float* __restrict__ img2) {
    const float G[11] = GW;

    extern __shared__ float smem[];
    float* sI1 = smem;                       // RH * RS
    float* sI2 = sI1 + RH * RS;              // RH * RS
    float* hb  = sI2 + RH * RS;              // 5 * RH * HS

    const int tid   = threadIdx.x;
    const int plane = blockIdx.z;
    const int x0    = blockIdx.x * TILE;
    const int y0    = blockIdx.y * TILE;

    const float* p1 = img1 + (size_t)plane * (IMG_W * IMG_H);
    const float* p2 = img2 + (size_t)plane * (IMG_W * IMG_H);

    // ---- Phase 1: load raw i1,i2 region (zero padded at image borders) ----
    for (int idx = tid; idx < RH * RW; idx += 512) {
        int ly = idx / RW;
        int lx = idx - ly * RW;
        int gx = x0 - HALO + lx;
        int gy = y0 - HALO + ly;
        float a = 0.f, b = 0.f;
        if ((unsigned)gx < IMG_W && (unsigned)gy < IMG_H) {
            int g = gy * IMG_W + gx;
            a = p1[g];
            b = p2[g];
        }
        sI1[ly * RS + lx] = a;
        sI2[ly * RS + lx] = b;
    }
    __syncthreads();

    // ---- Phase 2: horizontal conv of 5 quantities (products formed on the
    //      fly, once per raw pixel). 8 threads/row, 8 outputs/thread. ----
    {
        const int xs = (tid & 7) * 8;        // x segment start
        for (int row = tid >> 3; row < RH; row += 64) {
            float acc[5][8];
            #pragma unroll
            for (int q = 0; q < 5; q++)
                #pragma unroll
                for (int j = 0; j < 8; j++) acc[q][j] = 0.f;

            const float* r1 = sI1 + row * RS + xs;
            const float* r2 = sI2 + row * RS + xs;
            #pragma unroll
            for (int k = 0; k < 18; k++) {
                float a = r1[k];
                float b = r2[k];
                float aa = a * a;
                float bb = b * b;
                float ab = a * b;
                #pragma unroll
                for (int j = 0; j < 8; j++) {
                    int t = k - j;
                    if (t >= 0 && t < 11) {
                        float w = G[t];
                        acc[0][j] = fmaf(w, a,  acc[0][j]);
                        acc[1][j] = fmaf(w, b,  acc[1][j]);
                        acc[2][j] = fmaf(w, aa, acc[2][j]);
                        acc[3][j] = fmaf(w, bb, acc[3][j]);
                        acc[4][j] = fmaf(w, ab, acc[4][j]);
                    }
                }
            }
            #pragma unroll
            for (int q = 0; q < 5; q++) {
                float* dst = hb + q * (RH * HS) + row * HS + xs;
                #pragma unroll
                for (int j = 0; j < 8; j++) dst[j] = acc[q][j];
            }
        }
    }
    __syncthreads();

    // ---- Phase 3: vertical conv + SSIM epilogue. Each thread owns one x
    //      column and 8 consecutive y outputs. ----
    float psum = 0.f;
    {
        const int x     = tid & 63;
        const int ybase = (tid >> 6) * 8;
        const float* base = hb + ybase * HS + x;

        float mu1[8], mu2[8], e11[8], e22[8], e12[8];
        vpass(base + 0 * (RH * HS), mu1);
        vpass(base + 1 * (RH * HS), mu2);
        vpass(base + 2 * (RH * HS), e11);
        vpass(base + 3 * (RH * HS), e22);
        vpass(base + 4 * (RH * HS), e12);

        #pragma unroll
        for (int j = 0; j < 8; j++) {
            float m1   = mu1[j], m2 = mu2[j];
            float m1m1 = m1 * m1;
            float m2m2 = m2 * m2;
            float m1m2 = m1 * m2;
            float sig1  = e11[j] - m1m1;
            float sig2  = e22[j] - m2m2;
            float sig12 = e12[j] - m1m2;
            float num = (2.f * m1m2 + C1_) * (2.f * sig12 + C2_);
            float den = (m1m1 + m2m2 + C1_) * (sig1 + sig2 + C2_);
            psum += __fdividef(num, den);
        }
    }

    // ---- Phase 4: block reduction, one double atomic per block ----
    #pragma unroll
    for (int off = 16; off; off >>= 1)
        psum += __shfl_down_sync(0xffffffffu, psum, off);
    __syncthreads();                 // smem reuse for partials
    if ((tid & 31) == 0) sI1[tid >> 5] = psum;
    __syncthreads();
    if (tid < 32) {
        float v = (tid < 16) ? sI1[tid] : 0.f;
        #pragma unroll
        for (int off = 8; off; off >>= 1)
            v += __shfl_down_sync(0xffffffffu, v, off);
        if (tid == 0) atomicAdd(&g_sum, (double)v);
    }
}

extern "C" void kernel_launch(void* const* d_in, const int* in_sizes, int n_in,
                              void* d_out, int out_size) {
    const float* img1 = (const float*)d_in[0];
    const float* img2 = (const float*)d_in[1];
    float* out = (float*)d_out;

    const size_t smem_bytes = (size_t)(2 * RH * RS + 5 * RH * HS) * sizeof(float);
    cudaFuncSetAttribute(ssim_kernel,
                         cudaFuncAttributeMaxDynamicSharedMemorySize,
                         (int)smem_bytes);

    zero_kernel<<<1, 1>>>();
    dim3 grid(IMG_W / TILE, IMG_H / TILE, NPLANES);
    ssim_kernel<<<grid, 512, smem_bytes>>>(img1, img2);
    finalize_kernel<<<1, 1>>>(out);
}

// round 2
// speedup vs baseline: 1.5929x; 1.5929x over previous
#include <cuda_runtime.h>
#include <cstdint>

// ---------------------------------------------------------------------------
// SSIM loss, fused tiled kernel, R2: occupancy-focused.
//   - horizontal 1-D conv of the 5 quantities read DIRECTLY from gmem
//     (no raw-image smem stage) -> smem = hbuf only (96.2 KB) -> 2 CTAs/SM
//   - vertical 1-D conv + SSIM epilogue + block reduction unchanged
// Shapes fixed: (16,3,512,512) fp32 inputs, scalar fp32 out.
// ---------------------------------------------------------------------------

#define IMG_W   512
#define IMG_H   512
#define NPLANES 48
#define NPIX    (48LL * 512 * 512)

#define TILE 64
#define HALO 5
#define RH   (TILE + 2 * HALO)           // 74 rows of horizontal output
#define HS   65                          // hbuf row stride
#define HBUF_FLOATS (5 * RH * HS)        // 24050
#define NJOBS (RH * 8)                   // 592 horizontal jobs (8 segs/row)

#define GW {0.00102838f, 0.00759876f, 0.03600077f, 0.10936070f, 0.21300554f, \
            0.26601172f, 0.21300554f, 0.10936070f, 0.03600077f, 0.00759876f, \
            0.00102838f}

#define C1_ 0.0001f
#define C2_ 0.0009f

__device__ double g_sum;

__global__ void zero_kernel() { g_sum = 0.0; }

__global__ void finalize_kernel(float* out) {
    out[0] = (float)(1.0 - g_sum / (double)NPIX);
}

// Vertical conv pass: 18 strided SMEM loads -> 8 outputs (register tiling).
__device__ __forceinline__ void vpass(const float* __restrict__ col, float out[8]) {
    const float G[11] = GW;
    #pragma unroll
    for (int j = 0; j < 8; j++) out[j] = 0.f;
    #pragma unroll
    for (int k = 0; k < 18; k++) {
        float v = col[k * HS];
        #pragma unroll
        for (int j = 0; j < 8; j++) {
            int t = k - j;
            if (t >= 0 && t < 11) out[j] = fmaf(G[t], v, out[j]);
        }
    }
}

__global__ __launch_bounds__(512, 2)
void ssim_kernel(const float* __restrict__ img1, const float* __restrict__ img2) {
    const float G[11] = GW;

    extern __shared__ float hb[];        // 5 * RH * HS

    const int tid   = threadIdx.x;
    const int plane = blockIdx.z;
    const int x0    = blockIdx.x * TILE;
    const int y0    = blockIdx.y * TILE;

    const float* p1 = img1 + (size_t)plane * (IMG_W * IMG_H);
    const float* p2 = img2 + (size_t)plane * (IMG_W * IMG_H);

    // Interior tiles need no x bounds checks (x0-5 >= 0 and x0+68 <= 511).
    const bool xin = (x0 >= 8) && (x0 <= IMG_W - TILE - 8);

    // ---- Phase A: horizontal conv of 5 quantities straight from gmem.
    //      job = row * 8 + seg ; each job: 18 (a,b) loads -> 8 outputs. ----
    for (int job = tid; job < NJOBS; job += 512) {
        const int row = job >> 3;
        const int xs  = (job & 7) * 8;
        const int gy  = y0 - HALO + row;
        const bool yok = ((unsigned)gy < IMG_H);

        float acc[5][8];
        #pragma unroll
        for (int q = 0; q < 5; q++)
            #pragma unroll
            for (int j = 0; j < 8; j++) acc[q][j] = 0.f;

        const int xbase = x0 - HALO + xs;
        const float* r1 = p1 + (size_t)gy * IMG_W + xbase;
        const float* r2 = p2 + (size_t)gy * IMG_W + xbase;

        if (yok) {
            #pragma unroll
            for (int k = 0; k < 18; k++) {
                float a, b;
                if (xin || (unsigned)(xbase + k) < IMG_W) {
                    a = __ldg(r1 + k);
                    b = __ldg(r2 + k);
                } else {
                    a = 0.f; b = 0.f;
                }
                float aa = a * a;
                float bb = b * b;
                float ab = a * b;
                #pragma unroll
                for (int j = 0; j < 8; j++) {
                    int t = k - j;
                    if (t >= 0 && t < 11) {
                        float w = G[t];
                        acc[0][j] = fmaf(w, a,  acc[0][j]);
                        acc[1][j] = fmaf(w, b,  acc[1][j]);
                        acc[2][j] = fmaf(w, aa, acc[2][j]);
                        acc[3][j] = fmaf(w, bb, acc[3][j]);
                        acc[4][j] = fmaf(w, ab, acc[4][j]);
                    }
                }
            }
        }

        #pragma unroll
        for (int q = 0; q < 5; q++) {
            float* dst = hb + q * (RH * HS) + row * HS + xs;
            #pragma unroll
            for (int j = 0; j < 8; j++) dst[j] = acc[q][j];
        }
    }
    __syncthreads();

    // ---- Phase B: vertical conv + SSIM epilogue. One x column, 8 y
    //      outputs per thread. ----
    float psum = 0.f;
    {
        const int x     = tid & 63;
        const int ybase = (tid >> 6) * 8;
        const float* base = hb + ybase * HS + x;

        float mu1[8], mu2[8], e11[8], e22[8], e12[8];
        vpass(base + 0 * (RH * HS), mu1);
        vpass(base + 1 * (RH * HS), mu2);
        vpass(base + 2 * (RH * HS), e11);
        vpass(base + 3 * (RH * HS), e22);
        vpass(base + 4 * (RH * HS), e12);

        #pragma unroll
        for (int j = 0; j < 8; j++) {
            float m1   = mu1[j], m2 = mu2[j];
            float m1m1 = m1 * m1;
            float m2m2 = m2 * m2;
            float m1m2 = m1 * m2;
            float sig1  = e11[j] - m1m1;
            float sig2  = e22[j] - m2m2;
            float sig12 = e12[j] - m1m2;
            float num = (2.f * m1m2 + C1_) * (2.f * sig12 + C2_);
            float den = (m1m1 + m2m2 + C1_) * (sig1 + sig2 + C2_);
            psum += __fdividef(num, den);
        }
    }

    // ---- Phase C: block reduction, one double atomic per block ----
    #pragma unroll
    for (int off = 16; off; off >>= 1)
        psum += __shfl_down_sync(0xffffffffu, psum, off);
    __syncthreads();                 // all hbuf reads done; reuse as scratch
    if ((tid & 31) == 0) hb[tid >> 5] = psum;
    __syncthreads();
    if (tid < 32) {
        float v = (tid < 16) ? hb[tid] : 0.f;
        #pragma unroll
        for (int off = 8; off; off >>= 1)
            v += __shfl_down_sync(0xffffffffu, v, off);
        if (tid == 0) atomicAdd(&g_sum, (double)v);
    }
}

extern "C" void kernel_launch(void* const* d_in, const int* in_sizes, int n_in,
                              void* d_out, int out_size) {
    const float* img1 = (const float*)d_in[0];
    const float* img2 = (const float*)d_in[1];
    float* out = (float*)d_out;

    const size_t smem_bytes = (size_t)HBUF_FLOATS * sizeof(float);   // 96200 B
    cudaFuncSetAttribute(ssim_kernel,
                         cudaFuncAttributeMaxDynamicSharedMemorySize,
                         (int)smem_bytes);

    zero_kernel<<<1, 1>>>();
    dim3 grid(IMG_W / TILE, IMG_H / TILE, NPLANES);
    ssim_kernel<<<grid, 512, smem_bytes>>>(img1, img2);
    finalize_kernel<<<1, 1>>>(out);
}

// round 3
// speedup vs baseline: 1.7771x; 1.1156x over previous
#include <cuda_runtime.h>
#include <cstdint>

// ---------------------------------------------------------------------------
// SSIM loss, fused tiled kernel, R3.
//   - phase A: horizontal 1-D conv of 5 quantities straight from gmem,
//     vectorized LDG.128 loads (interior) + STS.128 stores (stride 68)
//   - phase B: vertical 1-D conv + SSIM epilogue (register tiling, 8 out/thr)
//   - accumulator reset folded into finalize (no zero_kernel)
// Shapes fixed: (16,3,512,512) fp32 inputs, scalar fp32 out.
// ---------------------------------------------------------------------------

#define IMG_W   512
#define IMG_H   512
#define NPLANES 48
#define NPIX    (48LL * 512 * 512)

#define TILE 64
#define HALO 5
#define RH   (TILE + 2 * HALO)           // 74 rows of horizontal output
#define HS   68                          // hbuf row stride (16B-aligned rows)
#define QS   (RH * HS)                   // floats per quantity plane (5032)
#define HBUF_FLOATS (5 * QS)             // 25160 -> 100640 B
#define NJOBS (RH * 8)                   // 592 horizontal jobs (8 segs/row)

#define GW {0.00102838f, 0.00759876f, 0.03600077f, 0.10936070f, 0.21300554f, \
            0.26601172f, 0.21300554f, 0.10936070f, 0.03600077f, 0.00759876f, \
            0.00102838f}

#define C1_ 0.0001f
#define C2_ 0.0009f

__device__ double g_sum;   // static-init 0; finalize resets after reading

__global__ void finalize_kernel(float* out) {
    out[0] = (float)(1.0 - g_sum / (double)NPIX);
    g_sum = 0.0;           // ready for next graph replay
}

// Vertical conv pass: 18 strided SMEM loads -> 8 outputs (register tiling).
__device__ __forceinline__ void vpass(const float* __restrict__ col, float out[8]) {
    const float G[11] = GW;
    #pragma unroll
    for (int j = 0; j < 8; j++) out[j] = 0.f;
    #pragma unroll
    for (int k = 0; k < 18; k++) {
        float v = col[k * HS];
        #pragma unroll
        for (int j = 0; j < 8; j++) {
            int t = k - j;
            if (t >= 0 && t < 11) out[j] = fmaf(G[t], v, out[j]);
        }
    }
}

__global__ __launch_bounds__(512, 2)
void ssim_kernel(const float* __restrict__ img1, const float* __restrict__ img2) {
    const float G[11] = GW;

    extern __shared__ float hb[];        // 5 * QS

    const int tid   = threadIdx.x;
    const int plane = blockIdx.z;
    const int x0    = blockIdx.x * TILE;
    const int y0    = blockIdx.y * TILE;

    const float* p1 = img1 + (size_t)plane * (IMG_W * IMG_H);
    const float* p2 = img2 + (size_t)plane * (IMG_W * IMG_H);

    // ---- Phase A: horizontal conv of 5 quantities straight from gmem. ----
    for (int job = tid; job < NJOBS; job += 512) {
        const int row = job >> 3;
        const int xs  = (job & 7) * 8;
        const int gy  = y0 - HALO + row;
        const bool yok = ((unsigned)gy < IMG_H);

        const int xbase = x0 - HALO + xs;     // first tap x (may be <0)
        const int a0    = xbase - 3;          // 16B-aligned vector base
        const bool vec_ok = yok && (a0 >= 0) && (a0 + 20 < IMG_W);

        float v1[18], v2[18];
        if (vec_ok) {
            const float* b1 = p1 + (size_t)gy * IMG_W + a0;
            const float* b2 = p2 + (size_t)gy * IMG_W + a0;
            float t1[21], t2[21];
            #pragma unroll
            for (int i = 0; i < 5; i++) {
                float4 q1 = __ldg((const float4*)(b1 + 4 * i));
                float4 q2 = __ldg((const float4*)(b2 + 4 * i));
                t1[4*i+0] = q1.x; t1[4*i+1] = q1.y; t1[4*i+2] = q1.z; t1[4*i+3] = q1.w;
                t2[4*i+0] = q2.x; t2[4*i+1] = q2.y; t2[4*i+2] = q2.z; t2[4*i+3] = q2.w;
            }
            t1[20] = __ldg(b1 + 20);
            t2[20] = __ldg(b2 + 20);
            #pragma unroll
            for (int k = 0; k < 18; k++) { v1[k] = t1[k + 3]; v2[k] = t2[k + 3]; }
        } else if (yok) {
            const float* r1 = p1 + (size_t)gy * IMG_W + xbase;
            const float* r2 = p2 + (size_t)gy * IMG_W + xbase;
            #pragma unroll
            for (int k = 0; k < 18; k++) {
                bool ok = ((unsigned)(xbase + k) < IMG_W);
                v1[k] = ok ? __ldg(r1 + k) : 0.f;
                v2[k] = ok ? __ldg(r2 + k) : 0.f;
            }
        } else {
            #pragma unroll
            for (int k = 0; k < 18; k++) { v1[k] = 0.f; v2[k] = 0.f; }
        }

        float acc[5][8];
        #pragma unroll
        for (int q = 0; q < 5; q++)
            #pragma unroll
            for (int j = 0; j < 8; j++) acc[q][j] = 0.f;

        #pragma unroll
        for (int k = 0; k < 18; k++) {
            float a = v1[k];
            float b = v2[k];
            float aa = a * a;
            float bb = b * b;
            float ab = a * b;
            #pragma unroll
            for (int j = 0; j < 8; j++) {
                int t = k - j;
                if (t >= 0 && t < 11) {
                    float w = G[t];
                    acc[0][j] = fmaf(w, a,  acc[0][j]);
                    acc[1][j] = fmaf(w, b,  acc[1][j]);
                    acc[2][j] = fmaf(w, aa, acc[2][j]);
                    acc[3][j] = fmaf(w, bb, acc[3][j]);
                    acc[4][j] = fmaf(w, ab, acc[4][j]);
                }
            }
        }

        // 16B-aligned vector stores (HS=68, xs mult of 8, base aligned)
        #pragma unroll
        for (int q = 0; q < 5; q++) {
            float* dst = hb + q * QS + row * HS + xs;
            *(float4*)(dst + 0) = make_float4(acc[q][0], acc[q][1], acc[q][2], acc[q][3]);
            *(float4*)(dst + 4) = make_float4(acc[q][4], acc[q][5], acc[q][6], acc[q][7]);
        }
    }
    __syncthreads();

    // ---- Phase B: vertical conv + SSIM epilogue. One x column, 8 y
    //      outputs per thread. ----
    float psum = 0.f;
    {
        const int x     = tid & 63;
        const int ybase = (tid >> 6) * 8;
        const float* base = hb + ybase * HS + x;

        float mu1[8], mu2[8], e11[8], e22[8], e12[8];
        vpass(base + 0 * QS, mu1);
        vpass(base + 1 * QS, mu2);
        vpass(base + 2 * QS, e11);
        vpass(base + 3 * QS, e22);
        vpass(base + 4 * QS, e12);

        #pragma unroll
        for (int j = 0; j < 8; j++) {
            float m1   = mu1[j], m2 = mu2[j];
            float m1m1 = m1 * m1;
            float m2m2 = m2 * m2;
            float m1m2 = m1 * m2;
            float sig1  = e11[j] - m1m1;
            float sig2  = e22[j] - m2m2;
            float sig12 = e12[j] - m1m2;
            float num = (2.f * m1m2 + C1_) * (2.f * sig12 + C2_);
            float den = (m1m1 + m2m2 + C1_) * (sig1 + sig2 + C2_);
            psum += __fdividef(num, den);
        }
    }

    // ---- Phase C: block reduction, one double atomic per block ----
    #pragma unroll
    for (int off = 16; off; off >>= 1)
        psum += __shfl_down_sync(0xffffffffu, psum, off);
    __syncthreads();                 // all hbuf reads done; reuse as scratch
    if ((tid & 31) == 0) hb[tid >> 5] = psum;
    __syncthreads();
    if (tid < 32) {
        float v = (tid < 16) ? hb[tid] : 0.f;
        #pragma unroll
        for (int off = 8; off; off >>= 1)
            v += __shfl_down_sync(0xffffffffu, v, off);
        if (tid == 0) atomicAdd(&g_sum, (double)v);
    }
}

extern "C" void kernel_launch(void* const* d_in, const int* in_sizes, int n_in,
                              void* d_out, int out_size) {
    const float* img1 = (const float*)d_in[0];
    const float* img2 = (const float*)d_in[1];
    float* out = (float*)d_out;

    const size_t smem_bytes = (size_t)HBUF_FLOATS * sizeof(float);   // 100640 B
    cudaFuncSetAttribute(ssim_kernel,
                         cudaFuncAttributeMaxDynamicSharedMemorySize,
                         (int)smem_bytes);

    dim3 grid(IMG_W / TILE, IMG_H / TILE, NPLANES);
    ssim_kernel<<<grid, 512, smem_bytes>>>(img1, img2);
    finalize_kernel<<<1, 1>>>(out);
}

// round 4
// speedup vs baseline: 2.0577x; 1.1579x over previous
#include <cuda_runtime.h>
#include <cstdint>

// ---------------------------------------------------------------------------
// SSIM loss, fused tiled kernel, R4.
//   - single kernel per call: last-block finalize (counter + threadfence)
//   - phase A: horizontal conv, 4-output jobs (better barrier balance),
//     vectorized LDG.128 + STS.128
//   - phase B: vertical conv + SSIM epilogue (8 outputs/thread)
// Shapes fixed: (16,3,512,512) fp32 inputs, scalar fp32 out.
// ---------------------------------------------------------------------------

#define IMG_W   512
#define IMG_H   512
#define NPLANES 48
#define NPIX    (48LL * 512 * 512)
#define NBLOCKS (8 * 8 * 48)             // 3072

#define TILE 64
#define HALO 5
#define RH   (TILE + 2 * HALO)           // 74 rows of horizontal output
#define HS   68                          // hbuf row stride (16B-aligned rows)
#define QS   (RH * HS)                   // floats per quantity plane
#define HBUF_FLOATS (5 * QS)             // 25160 -> 100640 B
#define NJOBS (RH * 16)                  // 1184 jobs (16 segs of 4 outputs)

#define GW {0.00102838f, 0.00759876f, 0.03600077f, 0.10936070f, 0.21300554f, \
            0.26601172f, 0.21300554f, 0.10936070f, 0.03600077f, 0.00759876f, \
            0.00102838f}

#define C1_ 0.0001f
#define C2_ 0.0009f

__device__ double g_sum;            // static-init 0
__device__ unsigned int g_count;    // static-init 0

// Vertical conv pass: 18 strided SMEM loads -> 8 outputs (register tiling).
__device__ __forceinline__ void vpass(const float* __restrict__ col, float out[8]) {
    const float G[11] = GW;
    #pragma unroll
    for (int j = 0; j < 8; j++) out[j] = 0.f;
    #pragma unroll
    for (int k = 0; k < 18; k++) {
        float v = col[k * HS];
        #pragma unroll
        for (int j = 0; j < 8; j++) {
            int t = k - j;
            if (t >= 0 && t < 11) out[j] = fmaf(G[t], v, out[j]);
        }
    }
}

__global__ __launch_bounds__(512, 2)
void ssim_kernel(const float* __restrict__ img1, const float* __restrict__ img2,
                 float* __restrict__ out) {
    const float G[11] = GW;

    extern __shared__ float hb[];        // 5 * QS

    const int tid   = threadIdx.x;
    const int plane = blockIdx.z;
    const int x0    = blockIdx.x * TILE;
    const int y0    = blockIdx.y * TILE;

    const float* p1 = img1 + (size_t)plane * (IMG_W * IMG_H);
    const float* p2 = img2 + (size_t)plane * (IMG_W * IMG_H);

    // ---- Phase A: horizontal conv of 5 quantities straight from gmem.
    //      Job = 4 consecutive x outputs of one row: 14 taps each. ----
    for (int job = tid; job < NJOBS; job += 512) {
        const int row = job >> 4;
        const int xs  = (job & 15) * 4;
        const int gy  = y0 - HALO + row;
        const bool yok = ((unsigned)gy < IMG_H);

        const int xbase = x0 - HALO + xs;     // first tap x (may be <0)
        const int a0    = xbase - 3;          // 16B-aligned vector base
        const bool vec_ok = yok && (a0 >= 0) && (a0 + 16 < IMG_W);

        float v1[14], v2[14];
        if (vec_ok) {
            const float* b1 = p1 + (size_t)gy * IMG_W + a0;
            const float* b2 = p2 + (size_t)gy * IMG_W + a0;
            float t1[17], t2[17];
            #pragma unroll
            for (int i = 0; i < 4; i++) {
                float4 q1 = __ldg((const float4*)(b1 + 4 * i));
                float4 q2 = __ldg((const float4*)(b2 + 4 * i));
                t1[4*i+0] = q1.x; t1[4*i+1] = q1.y; t1[4*i+2] = q1.z; t1[4*i+3] = q1.w;
                t2[4*i+0] = q2.x; t2[4*i+1] = q2.y; t2[4*i+2] = q2.z; t2[4*i+3] = q2.w;
            }
            t1[16] = __ldg(b1 + 16);
            t2[16] = __ldg(b2 + 16);
            #pragma unroll
            for (int k = 0; k < 14; k++) { v1[k] = t1[k + 3]; v2[k] = t2[k + 3]; }
        } else if (yok) {
            const float* r1 = p1 + (size_t)gy * IMG_W + xbase;
            const float* r2 = p2 + (size_t)gy * IMG_W + xbase;
            #pragma unroll
            for (int k = 0; k < 14; k++) {
                bool ok = ((unsigned)(xbase + k) < IMG_W);
                v1[k] = ok ? __ldg(r1 + k) : 0.f;
                v2[k] = ok ? __ldg(r2 + k) : 0.f;
            }
        } else {
            #pragma unroll
            for (int k = 0; k < 14; k++) { v1[k] = 0.f; v2[k] = 0.f; }
        }

        float acc[5][4];
        #pragma unroll
        for (int q = 0; q < 5; q++)
            #pragma unroll
            for (int j = 0; j < 4; j++) acc[q][j] = 0.f;

        #pragma unroll
        for (int k = 0; k < 14; k++) {
            float a = v1[k];
            float b = v2[k];
            float aa = a * a;
            float bb = b * b;
            float ab = a * b;
            #pragma unroll
            for (int j = 0; j < 4; j++) {
                int t = k - j;
                if (t >= 0 && t < 11) {
                    float w = G[t];
                    acc[0][j] = fmaf(w, a,  acc[0][j]);
                    acc[1][j] = fmaf(w, b,  acc[1][j]);
                    acc[2][j] = fmaf(w, aa, acc[2][j]);
                    acc[3][j] = fmaf(w, bb, acc[3][j]);
                    acc[4][j] = fmaf(w, ab, acc[4][j]);
                }
            }
        }

        // one STS.128 per quantity (xs*4B is 16B-aligned, HS=68)
        #pragma unroll
        for (int q = 0; q < 5; q++) {
            float* dst = hb + q * QS + row * HS + xs;
            *(float4*)dst = make_float4(acc[q][0], acc[q][1], acc[q][2], acc[q][3]);
        }
    }
    __syncthreads();

    // ---- Phase B: vertical conv + SSIM epilogue. One x column, 8 y
    //      outputs per thread. ----
    float psum = 0.f;
    {
        const int x     = tid & 63;
        const int ybase = (tid >> 6) * 8;
        const float* base = hb + ybase * HS + x;

        float mu1[8], mu2[8], e11[8], e22[8], e12[8];
        vpass(base + 0 * QS, mu1);
        vpass(base + 1 * QS, mu2);
        vpass(base + 2 * QS, e11);
        vpass(base + 3 * QS, e22);
        vpass(base + 4 * QS, e12);

        #pragma unroll
        for (int j = 0; j < 8; j++) {
            float m1   = mu1[j], m2 = mu2[j];
            float m1m1 = m1 * m1;
            float m2m2 = m2 * m2;
            float m1m2 = m1 * m2;
            float sig1  = e11[j] - m1m1;
            float sig2  = e22[j] - m2m2;
            float sig12 = e12[j] - m1m2;
            float num = (2.f * m1m2 + C1_) * (2.f * sig12 + C2_);
            float den = (m1m1 + m2m2 + C1_) * (sig1 + sig2 + C2_);
            psum += __fdividef(num, den);
        }
    }

    // ---- Phase C: block reduction -> one double atomic; last block
    //      finalizes the scalar output and resets the accumulators. ----
    #pragma unroll
    for (int off = 16; off; off >>= 1)
        psum += __shfl_down_sync(0xffffffffu, psum, off);
    __syncthreads();                 // all hbuf reads done; reuse as scratch
    if ((tid & 31) == 0) hb[tid >> 5] = psum;
    __syncthreads();
    if (tid == 0) {
        float v = 0.f;
        #pragma unroll
        for (int w = 0; w < 16; w++) v += hb[w];
        atomicAdd(&g_sum, (double)v);
        __threadfence();
        unsigned int c = atomicAdd(&g_count, 1u);
        if (c == NBLOCKS - 1) {
            out[0] = (float)(1.0 - g_sum / (double)NPIX);
            g_sum   = 0.0;           // ready for next graph replay
            g_count = 0u;
        }
    }
}

extern "C" void kernel_launch(void* const* d_in, const int* in_sizes, int n_in,
                              void* d_out, int out_size) {
    const float* img1 = (const float*)d_in[0];
    const float* img2 = (const float*)d_in[1];
    float* out = (float*)d_out;

    const size_t smem_bytes = (size_t)HBUF_FLOATS * sizeof(float);   // 100640 B
    cudaFuncSetAttribute(ssim_kernel,
                         cudaFuncAttributeMaxDynamicSharedMemorySize,
                         (int)smem_bytes);

    dim3 grid(IMG_W / TILE, IMG_H / TILE, NPLANES);
    ssim_kernel<<<grid, 512, smem_bytes>>>(img1, img2, out);
}

// round 5
// speedup vs baseline: 2.2494x; 1.0931x over previous
#include <cuda_runtime.h>
#include <cuda_fp16.h>
#include <cstdint>

// ---------------------------------------------------------------------------
// SSIM loss, fused tiled kernel, R5: occupancy via fp16 hbuf + 256-thr CTAs.
//   - TILE 32x64, hbuf stored fp16 (fp32 accumulate) -> 26.6KB smem/CTA
//   - __launch_bounds__(256,5): 48-reg cap -> 5 CTAs/SM = 40 warps (62.5%)
//   - phase A: horizontal conv, two tap-batches to bound live registers
//   - phase B: vertical conv + SSIM epilogue, 8 outputs/thread
//   - last-block finalize in-kernel
// Shapes fixed: (16,3,512,512) fp32 inputs, scalar fp32 out.
// ---------------------------------------------------------------------------

#define IMG_W   512
#define IMG_H   512
#define NPLANES 48
#define NPIX    (48LL * 512 * 512)

#define TILE_X  32
#define TILE_Y  64
#define HALO 5
#define RH   (TILE_Y + 2 * HALO)         // 74 rows of horizontal output
#define HS   36                          // hbuf row stride in halfs (72B rows)
#define QS   (RH * HS)                   // halfs per quantity plane (2664)
#define HBUF_HALFS (5 * QS)              // 13320 -> 26640 B
#define NJOBS (RH * 8)                   // 592 jobs (8 segs of 4 outputs)
#define NBLOCKS (16 * 8 * 48)            // 6144

#define GW {0.00102838f, 0.00759876f, 0.03600077f, 0.10936070f, 0.21300554f, \
            0.26601172f, 0.21300554f, 0.10936070f, 0.03600077f, 0.00759876f, \
            0.00102838f}

#define C1_ 0.0001f
#define C2_ 0.0009f

__device__ double g_sum;            // static-init 0
__device__ unsigned int g_count;    // static-init 0

// Vertical conv pass: 18 strided fp16 SMEM loads -> 8 fp32 outputs.
__device__ __forceinline__ void vpass(const __half* __restrict__ col, float out[8]) {
    const float G[11] = GW;
    #pragma unroll
    for (int j = 0; j < 8; j++) out[j] = 0.f;
    #pragma unroll
    for (int k = 0; k < 18; k++) {
        float v = __half2float(col[k * HS]);
        #pragma unroll
        for (int j = 0; j < 8; j++) {
            int t = k - j;
            if (t >= 0 && t < 11) out[j] = fmaf(G[t], v, out[j]);
        }
    }
}

__device__ __forceinline__ void accum_tap(float a, float b, int k, float acc[5][4]) {
    const float G[11] = GW;
    float aa = a * a;
    float bb = b * b;
    float ab = a * b;
    #pragma unroll
    for (int j = 0; j < 4; j++) {
        int t = k - j;
        if (t >= 0 && t < 11) {
            float w = G[t];
            acc[0][j] = fmaf(w, a,  acc[0][j]);
            acc[1][j] = fmaf(w, b,  acc[1][j]);
            acc[2][j] = fmaf(w, aa, acc[2][j]);
            acc[3][j] = fmaf(w, bb, acc[3][j]);
            acc[4][j] = fmaf(w, ab, acc[4][j]);
        }
    }
}

__global__ __launch_bounds__(256, 5)
void ssim_kernel(const float* __restrict__ img1, const float* __restrict__ img2,
                 float* __restrict__ out) {
    extern __shared__ __half hb[];       // 5 * QS halfs
    __shared__ float red[8];

    const int tid   = threadIdx.x;
    const int plane = blockIdx.z;
    const int x0    = blockIdx.x * TILE_X;
    const int y0    = blockIdx.y * TILE_Y;

    const float* p1 = img1 + (size_t)plane * (IMG_W * IMG_H);
    const float* p2 = img2 + (size_t)plane * (IMG_W * IMG_H);

    // ---- Phase A: horizontal conv of 5 quantities straight from gmem.
    //      Job = 4 consecutive x outputs of one row (14 taps). ----
    for (int job = tid; job < NJOBS; job += 256) {
        const int row = job >> 3;
        const int xs  = (job & 7) * 4;
        const int gy  = y0 - HALO + row;
        const bool yok = ((unsigned)gy < IMG_H);

        const int xbase = x0 - HALO + xs;     // first tap x (may be <0)
        const int a0    = xbase - 3;          // 16B-aligned vector base
        const bool vec_ok = yok && (a0 >= 0) && (a0 + 16 < IMG_W);

        float acc[5][4];
        #pragma unroll
        for (int q = 0; q < 5; q++)
            #pragma unroll
            for (int j = 0; j < 4; j++) acc[q][j] = 0.f;

        if (vec_ok) {
            const float* b1 = p1 + (size_t)gy * IMG_W + a0;
            const float* b2 = p2 + (size_t)gy * IMG_W + a0;
            // batch 1: t[0..7] -> taps k=0..4 (uses t[3..7])
            {
                float4 A0 = __ldg((const float4*)(b1 + 0));
                float4 A1 = __ldg((const float4*)(b1 + 4));
                float4 B0 = __ldg((const float4*)(b2 + 0));
                float4 B1 = __ldg((const float4*)(b2 + 4));
                float ta[8] = {A0.x, A0.y, A0.z, A0.w, A1.x, A1.y, A1.z, A1.w};
                float tb[8] = {B0.x, B0.y, B0.z, B0.w, B1.x, B1.y, B1.z, B1.w};
                #pragma unroll
                for (int k = 0; k < 5; k++)
                    accum_tap(ta[k + 3], tb[k + 3], k, acc);
            }
            // batch 2: t[8..16] -> taps k=5..13 (uses t[8..16])
            {
                float4 A2 = __ldg((const float4*)(b1 + 8));
                float4 A3 = __ldg((const float4*)(b1 + 12));
                float4 B2 = __ldg((const float4*)(b2 + 8));
                float4 B3 = __ldg((const float4*)(b2 + 12));
                float a16 = __ldg(b1 + 16);
                float b16 = __ldg(b2 + 16);
                float ta[9] = {A2.x, A2.y, A2.z, A2.w, A3.x, A3.y, A3.z, A3.w, a16};
                float tb[9] = {B2.x, B2.y, B2.z, B2.w, B3.x, B3.y, B3.z, B3.w, b16};
                #pragma unroll
                for (int k = 5; k < 14; k++)
                    accum_tap(ta[k - 5], tb[k - 5], k, acc);
            }
        } else if (yok) {
            const float* r1 = p1 + (size_t)gy * IMG_W + xbase;
            const float* r2 = p2 + (size_t)gy * IMG_W + xbase;
            #pragma unroll
            for (int k = 0; k < 14; k++) {
                bool ok = ((unsigned)(xbase + k) < IMG_W);
                float a = ok ? __ldg(r1 + k) : 0.f;
                float b = ok ? __ldg(r2 + k) : 0.f;
                accum_tap(a, b, k, acc);
            }
        }
        // else: out-of-image row -> zeros (acc already 0)

        #pragma unroll
        for (int q = 0; q < 5; q++) {
            __half2* dst = (__half2*)(hb + q * QS + row * HS + xs);
            dst[0] = __floats2half2_rn(acc[q][0], acc[q][1]);
            dst[1] = __floats2half2_rn(acc[q][2], acc[q][3]);
        }
    }
    __syncthreads();

    // ---- Phase B: vertical conv + SSIM epilogue. One x column, 8 y
    //      outputs per thread. ----
    float psum = 0.f;
    {
        const int x     = tid & 31;
        const int ybase = (tid >> 5) * 8;
        const __half* base = hb + ybase * HS + x;

        float mu1[8], mu2[8], e11[8], e22[8], e12[8];
        vpass(base + 0 * QS, mu1);
        vpass(base + 1 * QS, mu2);
        vpass(base + 2 * QS, e11);
        vpass(base + 3 * QS, e22);
        vpass(base + 4 * QS, e12);

        #pragma unroll
        for (int j = 0; j < 8; j++) {
            float m1   = mu1[j], m2 = mu2[j];
            float m1m1 = m1 * m1;
            float m2m2 = m2 * m2;
            float m1m2 = m1 * m2;
            float sig1  = e11[j] - m1m1;
            float sig2  = e22[j] - m2m2;
            float sig12 = e12[j] - m1m2;
            float num = (2.f * m1m2 + C1_) * (2.f * sig12 + C2_);
            float den = (m1m1 + m2m2 + C1_) * (sig1 + sig2 + C2_);
            psum += __fdividef(num, den);
        }
    }

    // ---- Phase C: block reduction -> one double atomic; last block
    //      finalizes the scalar output and resets the accumulators. ----
    #pragma unroll
    for (int off = 16; off; off >>= 1)
        psum += __shfl_down_sync(0xffffffffu, psum, off);
    if ((tid & 31) == 0) red[tid >> 5] = psum;
    __syncthreads();
    if (tid == 0) {
        float v = 0.f;
        #pragma unroll
        for (int w = 0; w < 8; w++) v += red[w];
        atomicAdd(&g_sum, (double)v);
        __threadfence();
        unsigned int c = atomicAdd(&g_count, 1u);
        if (c == NBLOCKS - 1) {
            out[0] = (float)(1.0 - g_sum / (double)NPIX);
            g_sum   = 0.0;           // ready for next graph replay
            g_count = 0u;
        }
    }
}

extern "C" void kernel_launch(void* const* d_in, const int* in_sizes, int n_in,
                              void* d_out, int out_size) {
    const float* img1 = (const float*)d_in[0];
    const float* img2 = (const float*)d_in[1];
    float* out = (float*)d_out;

    const size_t smem_bytes = (size_t)HBUF_HALFS * sizeof(__half);   // 26640 B
    cudaFuncSetAttribute(ssim_kernel,
                         cudaFuncAttributeMaxDynamicSharedMemorySize,
                         (int)smem_bytes);

    dim3 grid(IMG_W / TILE_X, IMG_H / TILE_Y, NPLANES);
    ssim_kernel<<<grid, 256, smem_bytes>>>(img1, img2, out);
}